// round 6
// baseline (speedup 1.0000x reference)
#include <cuda_runtime.h>
#include <math.h>

// Problem constants
#define B_   2
#define S_   2048
#define HID_ 2048
#define H_   16
#define HKV_ 16
#define DH_  128
#define NQKV ((H_ + 2*HKV_))          // 48 heads total in qkv
#define QKV_O (NQKV * DH_)            // 6144
#define MROWS (B_ * S_)               // 4096

// Scratch (allocation-free rule: __device__ globals)
__device__ float g_qkv[(size_t)B_ * S_ * QKV_O];     // [B,S,6144]
__device__ float g_attn[(size_t)B_ * S_ * H_ * DH_]; // [B,S,2048]

// ---------------------------------------------------------------------------
// Generic NT SGEMM: C[M,N] = A[M,K] * B[N,K]^T   (both K-contiguous, fp32)
// 128x128 tile, BK=16, 256 threads, 8x8 per-thread micro tile.
// Double-buffered smem, ONE __syncthreads per K-step; next-stage global
// loads (MLP=4) issued before compute.
// ROPE: apply rotary embedding in the epilogue (QKV projection only).
//   A tile of 128 N-columns is exactly one head's 128-dim slice, so a tile
//   is entirely q/k (nBase < 4096) or entirely v -> uniform branch.
// ---------------------------------------------------------------------------
template<bool A_FROM_ATTN, bool C_TO_QKV, bool ROPE>
__global__ __launch_bounds__(256, 2)
void sgemm_nt(const float* __restrict__ Ap, const float* __restrict__ Bp,
              float* __restrict__ Cp,
              const float* __restrict__ cosp, const float* __restrict__ sinp,
              int M, int N, int K)
{
    const float* A = A_FROM_ATTN ? (const float*)g_attn : Ap;
    float*       C = C_TO_QKV   ? (float*)g_qkv        : Cp;

    __shared__ float sA[2][16 * 128];
    __shared__ float sB[2][16 * 128];

    const int tid = threadIdx.x;
    const int tx = tid & 15;          // 0..15 -> n
    const int ty = tid >> 4;          // 0..15 -> m
    const int mBase = blockIdx.y * 128;
    const int nBase = blockIdx.x * 128;

    // Load mapping: 512 float4s per tile-stage per matrix; thread does 2.
    const int fr = tid >> 2;          // 0..63 (row, +64 for second load)
    const int fc = (tid & 3) * 4;     // k offset 0,4,8,12

    const float* Ag0 = A  + (size_t)(mBase + fr)      * K + fc;
    const float* Ag1 = A  + (size_t)(mBase + fr + 64) * K + fc;
    const float* Bg0 = Bp + (size_t)(nBase + fr)      * K + fc;
    const float* Bg1 = Bp + (size_t)(nBase + fr + 64) * K + fc;

    float acc[8][8];
#pragma unroll
    for (int i = 0; i < 8; i++)
#pragma unroll
        for (int j = 0; j < 8; j++) acc[i][j] = 0.f;

    const int nK = K >> 4;

    // Prologue: stage 0 into buffer 0
    float4 a0 = *(const float4*)(Ag0);
    float4 a1 = *(const float4*)(Ag1);
    float4 b0 = *(const float4*)(Bg0);
    float4 b1 = *(const float4*)(Bg1);
    sA[0][(fc + 0) * 128 + fr] = a0.x;
    sA[0][(fc + 1) * 128 + fr] = a0.y;
    sA[0][(fc + 2) * 128 + fr] = a0.z;
    sA[0][(fc + 3) * 128 + fr] = a0.w;
    sA[0][(fc + 0) * 128 + fr + 64] = a1.x;
    sA[0][(fc + 1) * 128 + fr + 64] = a1.y;
    sA[0][(fc + 2) * 128 + fr + 64] = a1.z;
    sA[0][(fc + 3) * 128 + fr + 64] = a1.w;
    sB[0][(fc + 0) * 128 + fr] = b0.x;
    sB[0][(fc + 1) * 128 + fr] = b0.y;
    sB[0][(fc + 2) * 128 + fr] = b0.z;
    sB[0][(fc + 3) * 128 + fr] = b0.w;
    sB[0][(fc + 0) * 128 + fr + 64] = b1.x;
    sB[0][(fc + 1) * 128 + fr + 64] = b1.y;
    sB[0][(fc + 2) * 128 + fr + 64] = b1.z;
    sB[0][(fc + 3) * 128 + fr + 64] = b1.w;
    __syncthreads();

    for (int kt = 0; kt < nK; kt++) {
        const int cur = kt & 1;
        const int nxt = cur ^ 1;

        if (kt + 1 < nK) {
            size_t ko = (size_t)(kt + 1) * 16;
            a0 = *(const float4*)(Ag0 + ko);
            a1 = *(const float4*)(Ag1 + ko);
            b0 = *(const float4*)(Bg0 + ko);
            b1 = *(const float4*)(Bg1 + ko);
        }

#pragma unroll
        for (int k = 0; k < 16; k++) {
            float ra[8], rb[8];
            float4 t0 = *(const float4*)&sA[cur][k * 128 + ty * 8];
            float4 t1 = *(const float4*)&sA[cur][k * 128 + ty * 8 + 4];
            ra[0]=t0.x; ra[1]=t0.y; ra[2]=t0.z; ra[3]=t0.w;
            ra[4]=t1.x; ra[5]=t1.y; ra[6]=t1.z; ra[7]=t1.w;
            float4 u0 = *(const float4*)&sB[cur][k * 128 + tx * 8];
            float4 u1 = *(const float4*)&sB[cur][k * 128 + tx * 8 + 4];
            rb[0]=u0.x; rb[1]=u0.y; rb[2]=u0.z; rb[3]=u0.w;
            rb[4]=u1.x; rb[5]=u1.y; rb[6]=u1.z; rb[7]=u1.w;
#pragma unroll
            for (int i = 0; i < 8; i++)
#pragma unroll
                for (int j = 0; j < 8; j++)
                    acc[i][j] = fmaf(ra[i], rb[j], acc[i][j]);
        }

        if (kt + 1 < nK) {
            sA[nxt][(fc + 0) * 128 + fr] = a0.x;
            sA[nxt][(fc + 1) * 128 + fr] = a0.y;
            sA[nxt][(fc + 2) * 128 + fr] = a0.z;
            sA[nxt][(fc + 3) * 128 + fr] = a0.w;
            sA[nxt][(fc + 0) * 128 + fr + 64] = a1.x;
            sA[nxt][(fc + 1) * 128 + fr + 64] = a1.y;
            sA[nxt][(fc + 2) * 128 + fr + 64] = a1.z;
            sA[nxt][(fc + 3) * 128 + fr + 64] = a1.w;
            sB[nxt][(fc + 0) * 128 + fr] = b0.x;
            sB[nxt][(fc + 1) * 128 + fr] = b0.y;
            sB[nxt][(fc + 2) * 128 + fr] = b0.z;
            sB[nxt][(fc + 3) * 128 + fr] = b0.w;
            sB[nxt][(fc + 0) * 128 + fr + 64] = b1.x;
            sB[nxt][(fc + 1) * 128 + fr + 64] = b1.y;
            sB[nxt][(fc + 2) * 128 + fr + 64] = b1.z;
            sB[nxt][(fc + 3) * 128 + fr + 64] = b1.w;
            __syncthreads();
        }
    }

    const bool doRope = ROPE && (nBase < (H_ + HKV_) * DH_);   // q/k region

#pragma unroll
    for (int i = 0; i < 8; i++) {
        if (doRope) {
            // seq position of this output row; head-internal col base = tx*8
            int s = (mBase + ty * 8 + i) & (S_ - 1);
            const float* cp = cosp + (size_t)s * DH_ + tx * 8;
            const float* sp = sinp + (size_t)s * DH_ + tx * 8;
#pragma unroll
            for (int p = 0; p < 4; p++) {
                float c  = cp[2 * p];    // cos repeated within a pair
                float sn = sp[2 * p];
                float x0 = acc[i][2 * p];
                float x1 = acc[i][2 * p + 1];
                acc[i][2 * p]     = x0 * c - x1 * sn;
                acc[i][2 * p + 1] = x1 * c + x0 * sn;
            }
        }
        size_t off = (size_t)(mBase + ty * 8 + i) * N + nBase + tx * 8;
        float4 c0 = { acc[i][0], acc[i][1], acc[i][2], acc[i][3] };
        float4 c1 = { acc[i][4], acc[i][5], acc[i][6], acc[i][7] };
        *(float4*)&C[off]     = c0;
        *(float4*)&C[off + 4] = c1;
    }
}

// ---------------------------------------------------------------------------
// Flash-style attention, BQ=128, BK=64. One block = 128 query rows of (b,h).
// 256 threads; per-thread: S micro-tile 8x4, O accumulator 8x8.
// K tile for iteration kt+1 is prefetched into registers during the PV phase
// of iteration kt and stored to smem after the loop-top barrier.
// Smem layout (floats):
//   sQ  [128][132]        offset 0      (16896)
//   sKV                   offset 16896  (8704)  K^T [128][68] then V [64][132]
//   sS  [128][68]         offset 25600  (8704)
//   sM[128] sL[128] sAl[128]  offsets 34304 / 34432 / 34560
// total 34688 floats = 138752 bytes  -> 1 CTA/SM
// ---------------------------------------------------------------------------
#define QS  132
#define KTS 68
#define VS  132
#define SS  68
#define ATTN_SMEM_BYTES (34688 * 4)

__global__ __launch_bounds__(256, 1)
void attn_kernel()
{
    extern __shared__ float sm[];
    float* sQ  = sm;
    float* sKV = sm + 16896;
    float* sS  = sm + 25600;
    float* sM  = sm + 34304;
    float* sL  = sm + 34432;
    float* sAl = sm + 34560;

    const int tid = threadIdx.x;
    const int tx = tid & 15;
    const int ty = tid >> 4;
    const int qt = blockIdx.x;     // query tile (16)
    const int h  = blockIdx.y;     // head (16)
    const int b  = blockIdx.z;     // batch (2)

    const float SCALE = 0.08838834764831845f;   // 1/sqrt(128)

    const float* Qg = g_qkv + ((size_t)(b * S_) + qt * 128) * QKV_O + h * DH_;
    const float* Kg = g_qkv + (size_t)(b * S_) * QKV_O + (H_ + h) * DH_;
    const float* Vg = g_qkv + (size_t)(b * S_) * QKV_O + (H_ + HKV_ + h) * DH_;

    // Per-thread K-load mapping (8 float4s cover the 64x128 K tile)
    const int kr_[1] = {0}; (void)kr_;

    // Load Q tile [128][128]
    for (int idx = tid; idx < 128 * 32; idx += 256) {
        int r = idx >> 5, c4 = (idx & 31) << 2;
        *(float4*)&sQ[r * QS + c4] = *(const float4*)&Qg[(size_t)r * QKV_O + c4];
    }
    if (tid < 128) { sM[tid] = -1.0e30f; sL[tid] = 0.f; }

    float acc[8][8];
#pragma unroll
    for (int i = 0; i < 8; i++)
#pragma unroll
        for (int c = 0; c < 8; c++) acc[i][c] = 0.f;

    const int r0  = ty * 8;        // 8 query rows per thread
    const int c0  = tx * 4;        // 4 S columns per thread
    const int cv0 = tx * 8;        // 8 O columns per thread

    // Prefetch K tile 0 into registers
    float4 kpre[8];
#pragma unroll
    for (int u = 0; u < 8; u++) {
        int idx = tid + u * 256;
        int r = idx >> 5, c4 = (idx & 31) << 2;
        kpre[u] = *(const float4*)&Kg[(size_t)r * QKV_O + c4];
    }

    for (int kt = 0; kt < 32; kt++) {
        const float* Vt = Vg + (size_t)(kt * 64) * QKV_O;

        __syncthreads();  // previous PV (V reads) done before overwriting sKV
        // Store prefetched K tile transposed: sKV[d][kr], stride 68
#pragma unroll
        for (int u = 0; u < 8; u++) {
            int idx = tid + u * 256;
            int r = idx >> 5, c4 = (idx & 31) << 2;
            sKV[(c4 + 0) * KTS + r] = kpre[u].x;
            sKV[(c4 + 1) * KTS + r] = kpre[u].y;
            sKV[(c4 + 2) * KTS + r] = kpre[u].z;
            sKV[(c4 + 3) * KTS + r] = kpre[u].w;
        }
        __syncthreads();

        // S = Q @ K^T  (128x64), 8x4 per thread
        float sacc[8][4];
#pragma unroll
        for (int i = 0; i < 8; i++)
#pragma unroll
            for (int j = 0; j < 4; j++) sacc[i][j] = 0.f;

        for (int d = 0; d < 128; d += 4) {
            float ka[4][4];
#pragma unroll
            for (int dd = 0; dd < 4; dd++) {
                float4 t = *(const float4*)&sKV[(d + dd) * KTS + c0];
                ka[dd][0]=t.x; ka[dd][1]=t.y; ka[dd][2]=t.z; ka[dd][3]=t.w;
            }
#pragma unroll
            for (int i = 0; i < 8; i++) {
                float4 q4 = *(const float4*)&sQ[(r0 + i) * QS + d];
                float qa[4] = { q4.x, q4.y, q4.z, q4.w };
#pragma unroll
                for (int dd = 0; dd < 4; dd++)
#pragma unroll
                    for (int j = 0; j < 4; j++)
                        sacc[i][j] = fmaf(qa[dd], ka[dd][j], sacc[i][j]);
            }
        }
#pragma unroll
        for (int i = 0; i < 8; i++) {
            float4 srow = { sacc[i][0]*SCALE, sacc[i][1]*SCALE,
                            sacc[i][2]*SCALE, sacc[i][3]*SCALE };
            *(float4*)&sS[(r0 + i) * SS + c0] = srow;
        }
        __syncthreads();

        // Load V tile row-major into sKV (K no longer needed);
        // these stores overlap with the softmax below.
        for (int idx = tid; idx < 64 * 32; idx += 256) {
            int r = idx >> 5, c4 = (idx & 31) << 2;
            *(float4*)&sKV[r * VS + c4] = *(const float4*)&Vt[(size_t)r * QKV_O + c4];
        }

        // Online softmax: 2 threads per row (32 cols each), shfl reduction.
        {
            int row = tid >> 1;        // 0..127
            int g   = tid & 1;         // 0..1 -> 32-element chunk
            float* rowp = &sS[row * SS + g * 32];
            float4 v[8];
            float mx = -1.0e30f;
#pragma unroll
            for (int q = 0; q < 8; q++) {
                v[q] = *(float4*)&rowp[q * 4];
                mx = fmaxf(mx, fmaxf(fmaxf(v[q].x, v[q].y), fmaxf(v[q].z, v[q].w)));
            }
            mx = fmaxf(mx, __shfl_xor_sync(0xFFFFFFFFu, mx, 1));
            float mold = sM[row];
            float mnew = fmaxf(mold, mx);
            float sum = 0.f;
#pragma unroll
            for (int q = 0; q < 8; q++) {
                v[q].x = __expf(v[q].x - mnew);
                v[q].y = __expf(v[q].y - mnew);
                v[q].z = __expf(v[q].z - mnew);
                v[q].w = __expf(v[q].w - mnew);
                sum += (v[q].x + v[q].y) + (v[q].z + v[q].w);
                *(float4*)&rowp[q * 4] = v[q];
            }
            sum += __shfl_xor_sync(0xFFFFFFFFu, sum, 1);
            if (g == 0) {
                float al = __expf(mold - mnew);
                sL[row] = sL[row] * al + sum;
                sM[row] = mnew;
                sAl[row] = al;
            }
        }
        __syncthreads();

        // Rescale accumulators
#pragma unroll
        for (int i = 0; i < 8; i++) {
            float al = sAl[r0 + i];
#pragma unroll
            for (int c = 0; c < 8; c++) acc[i][c] *= al;
        }

        // Prefetch next K tile into registers (latency hidden under PV)
        if (kt + 1 < 32) {
            const float* Kn = Kg + (size_t)((kt + 1) * 64) * QKV_O;
#pragma unroll
            for (int u = 0; u < 8; u++) {
                int idx = tid + u * 256;
                int r = idx >> 5, c4 = (idx & 31) << 2;
                kpre[u] = *(const float4*)&Kn[(size_t)r * QKV_O + c4];
            }
        }

        // O += P @ V
        for (int j = 0; j < 64; j++) {
            float4 v0 = *(const float4*)&sKV[j * VS + cv0];
            float4 v1 = *(const float4*)&sKV[j * VS + cv0 + 4];
#pragma unroll
            for (int i = 0; i < 8; i++) {
                float p = sS[(r0 + i) * SS + j];
                acc[i][0] = fmaf(p, v0.x, acc[i][0]);
                acc[i][1] = fmaf(p, v0.y, acc[i][1]);
                acc[i][2] = fmaf(p, v0.z, acc[i][2]);
                acc[i][3] = fmaf(p, v0.w, acc[i][3]);
                acc[i][4] = fmaf(p, v1.x, acc[i][4]);
                acc[i][5] = fmaf(p, v1.y, acc[i][5]);
                acc[i][6] = fmaf(p, v1.z, acc[i][6]);
                acc[i][7] = fmaf(p, v1.w, acc[i][7]);
            }
        }
    }

    // Write O (divide by final l)
    float* Og = g_attn + ((size_t)(b * S_) + qt * 128) * (H_ * DH_) + h * DH_;
#pragma unroll
    for (int i = 0; i < 8; i++) {
        float linv = 1.f / sL[r0 + i];
        float4 o0 = { acc[i][0]*linv, acc[i][1]*linv, acc[i][2]*linv, acc[i][3]*linv };
        float4 o1 = { acc[i][4]*linv, acc[i][5]*linv, acc[i][6]*linv, acc[i][7]*linv };
        size_t off = (size_t)(r0 + i) * (H_ * DH_) + cv0;
        *(float4*)&Og[off]     = o0;
        *(float4*)&Og[off + 4] = o1;
    }
}

// ---------------------------------------------------------------------------
// Launch
// ---------------------------------------------------------------------------
extern "C" void kernel_launch(void* const* d_in, const int* in_sizes, int n_in,
                              void* d_out, int out_size)
{
    const float* hs   = (const float*)d_in[0];  // [2,2048,2048]
    const float* cosp = (const float*)d_in[1];  // [2048,128]
    const float* sinp = (const float*)d_in[2];  // [2048,128]
    const float* wqkv = (const float*)d_in[3];  // [6144,2048]
    const float* wo   = (const float*)d_in[4];  // [2048,2048]
    float* out = (float*)d_out;                 // [2,2048,2048]

    // 1. QKV projection + fused RoPE: g_qkv = hs @ wqkv^T, then RoPE on q/k
    sgemm_nt<false, true, true><<<dim3(QKV_O / 128, MROWS / 128), 256>>>(
        hs, wqkv, nullptr, cosp, sinp, MROWS, QKV_O, HID_);

    // 2. Attention -> g_attn
    cudaFuncSetAttribute(attn_kernel,
                         cudaFuncAttributeMaxDynamicSharedMemorySize,
                         ATTN_SMEM_BYTES);
    attn_kernel<<<dim3(S_ / 128, H_, B_), 256, ATTN_SMEM_BYTES>>>();

    // 3. Output projection: out = g_attn @ wo^T
    sgemm_nt<true, false, false><<<dim3(HID_ / 128, MROWS / 128), 256>>>(
        nullptr, wo, out, nullptr, nullptr, MROWS, HID_, 2048);
}

// round 12
// speedup vs baseline: 1.4947x; 1.4947x over previous
#include <cuda_runtime.h>
#include <cuda_bf16.h>
#include <math.h>
#include <stdint.h>

// Problem constants
#define B_   2
#define S_   2048
#define HID_ 2048
#define H_   16
#define HKV_ 16
#define DH_  128
#define QKV_O 6144
#define MROWS 4096

// Scratch (allocation-free rule: __device__ globals)
__device__ float g_qkv[(size_t)B_ * S_ * QKV_O];     // [B,S,6144]
__device__ float g_attn[(size_t)B_ * S_ * H_ * DH_]; // [B,S,2048]

// ---------------------------------------------------------------------------
// Portable tensor-core primitives (sm_80+ PTX; legal on compute_103)
// ---------------------------------------------------------------------------
__device__ __forceinline__ uint32_t smem_u32(const void* p) {
    uint32_t a;
    asm("{ .reg .u64 t; cvta.to.shared.u64 t, %1; cvt.u32.u64 %0, t; }"
        : "=r"(a) : "l"(p));
    return a;
}
#define LDSM4(r, addr) \
    asm volatile("ldmatrix.sync.aligned.m8n8.x4.shared.b16 {%0,%1,%2,%3}, [%4];" \
        : "=r"((r)[0]), "=r"((r)[1]), "=r"((r)[2]), "=r"((r)[3]) : "r"(addr))
#define MMA_BF16(c, a, b0, b1) \
    asm volatile("mma.sync.aligned.m16n8k16.row.col.f32.bf16.bf16.f32 " \
        "{%0,%1,%2,%3}, {%4,%5,%6,%7}, {%8,%9}, {%0,%1,%2,%3};" \
        : "+f"((c)[0]), "+f"((c)[1]), "+f"((c)[2]), "+f"((c)[3]) \
        : "r"((a)[0]), "r"((a)[1]), "r"((a)[2]), "r"((a)[3]), "r"(b0), "r"(b1))
#define STS64(addr, u0, u1) \
    asm volatile("st.shared.v2.b32 [%0], {%1, %2};" \
        :: "r"(addr), "r"(u0), "r"(u1) : "memory")

// Split float4 -> bf16 hi pair-packed (h0,h1) + residual lo (l0,l1)
__device__ __forceinline__ void cvt_f4(const float4 f,
                                       uint32_t& h0, uint32_t& h1,
                                       uint32_t& l0, uint32_t& l1)
{
    __nv_bfloat16 bx = __float2bfloat16(f.x);
    __nv_bfloat16 by = __float2bfloat16(f.y);
    __nv_bfloat16 bz = __float2bfloat16(f.z);
    __nv_bfloat16 bw = __float2bfloat16(f.w);
    float rx = f.x - __bfloat162float(bx);
    float ry = f.y - __bfloat162float(by);
    float rz = f.z - __bfloat162float(bz);
    float rw = f.w - __bfloat162float(bw);
    __nv_bfloat162 hxy = __halves2bfloat162(bx, by);
    __nv_bfloat162 hzw = __halves2bfloat162(bz, bw);
    __nv_bfloat162 lxy = __floats2bfloat162_rn(rx, ry);
    __nv_bfloat162 lzw = __floats2bfloat162_rn(rz, rw);
    h0 = *reinterpret_cast<uint32_t*>(&hxy);
    h1 = *reinterpret_cast<uint32_t*>(&hzw);
    l0 = *reinterpret_cast<uint32_t*>(&lxy);
    l1 = *reinterpret_cast<uint32_t*>(&lzw);
}

// ---------------------------------------------------------------------------
// Tensor-core NT GEMM via mma.sync: C[M,N] = A[M,K]*B[N,K]^T, fp32 in/out.
// bf16 hi/lo split, 3 accumulation passes, fp32 register accumulators.
// Tile 128x128, BK=32, 512 threads (4x4 warps, 32x32 warp tile).
// Smem/stage: Ah,Al,Bh,Bl each [128 rows][32 bf16], row stride 80B
// (ldmatrix phase -> banks 20*r mod 32: conflict-free). Double buffered.
// RoPE fused into the fp32 epilogue for the QKV projection (K=2048 fixed).
// NOTE: occupancy pinned to 1 CTA/SM: (512,2) would cap regs at 64/thread
// and spill the 32 accumulators (live state ~100 regs).
// ---------------------------------------------------------------------------
#define GK        2048
#define NSTAGE    64                  // GK/32
#define ROWB      80                  // bytes per smem row
#define MATB      (128 * ROWB)        // 10240 bytes per matrix
#define STAGEB    (4 * MATB)          // 40960
#define GEMM_SMEM (2 * STAGEB)        // 81920

template<bool A_FROM_ATTN, bool C_TO_QKV, bool ROPE>
__global__ __launch_bounds__(512, 1)
void mma_gemm(const float* __restrict__ Ap, const float* __restrict__ Bp,
              float* __restrict__ Cp,
              const float* __restrict__ cosp, const float* __restrict__ sinp,
              int Ncols)
{
    extern __shared__ char smem[];
    const uint32_t sb = smem_u32(smem);
    const int tid  = threadIdx.x;
    const int lane = tid & 31;
    const int warp = tid >> 5;
    const int wm = warp >> 2;          // 0..3
    const int wn = warp & 3;           // 0..3
    const int mBase = blockIdx.y * 128;
    const int nBase = blockIdx.x * 128;

    const float* A = A_FROM_ATTN ? (const float*)g_attn : Ap;
    float*       C = C_TO_QKV   ? (float*)g_qkv        : Cp;

    // Staging: 1024 float4 per matrix per stage; thread does 2 each.
    const int i0 = tid, i1 = tid + 512;
    const float* gA0 = A  + (size_t)(mBase + (i0 >> 3)) * GK + (i0 & 7) * 4;
    const float* gA1 = A  + (size_t)(mBase + (i1 >> 3)) * GK + (i1 & 7) * 4;
    const float* gB0 = Bp + (size_t)(nBase + (i0 >> 3)) * GK + (i0 & 7) * 4;
    const float* gB1 = Bp + (size_t)(nBase + (i1 >> 3)) * GK + (i1 & 7) * 4;
    const uint32_t st0 = (uint32_t)((i0 >> 3) * ROWB + (i0 & 7) * 8);
    const uint32_t st1 = (uint32_t)((i1 >> 3) * ROWB + (i1 & 7) * 8);

    // ldmatrix per-lane base offsets
    const uint32_t aOff = (uint32_t)((wm * 32 + (lane & 15)) * ROWB + (lane >> 4) * 16);
    const uint32_t bOff = (uint32_t)((wn * 32 + ((lane >> 3) & 2) * 4 + (lane & 7)) * ROWB
                                     + ((lane >> 3) & 1) * 16);

    float c[2][4][4];
#pragma unroll
    for (int mt = 0; mt < 2; mt++)
#pragma unroll
        for (int nt = 0; nt < 4; nt++)
#pragma unroll
            for (int q = 0; q < 4; q++) c[mt][nt][q] = 0.f;

    // Prologue: stage 0 into buffer 0
    {
        float4 av0 = *(const float4*)gA0;
        float4 av1 = *(const float4*)gA1;
        float4 bv0 = *(const float4*)gB0;
        float4 bv1 = *(const float4*)gB1;
        uint32_t h0, h1, l0, l1;
        cvt_f4(av0, h0, h1, l0, l1);
        STS64(sb + st0, h0, h1);           STS64(sb + MATB + st0, l0, l1);
        cvt_f4(av1, h0, h1, l0, l1);
        STS64(sb + st1, h0, h1);           STS64(sb + MATB + st1, l0, l1);
        cvt_f4(bv0, h0, h1, l0, l1);
        STS64(sb + 2*MATB + st0, h0, h1);  STS64(sb + 3*MATB + st0, l0, l1);
        cvt_f4(bv1, h0, h1, l0, l1);
        STS64(sb + 2*MATB + st1, h0, h1);  STS64(sb + 3*MATB + st1, l0, l1);
    }
    __syncthreads();

    for (int s = 0; s < NSTAGE; s++) {
        float4 av0, av1, bv0, bv1;
        if (s + 1 < NSTAGE) {
            const size_t ko = (size_t)(s + 1) * 32;
            av0 = *(const float4*)(gA0 + ko);
            av1 = *(const float4*)(gA1 + ko);
            bv0 = *(const float4*)(gB0 + ko);
            bv1 = *(const float4*)(gB1 + ko);
        }

        const uint32_t buf = sb + (uint32_t)(s & 1) * STAGEB;
#pragma unroll
        for (int kb = 0; kb < 2; kb++) {
            const uint32_t ko = kb * 32;    // 16 bf16 = 32 bytes
            uint32_t ah[2][4], al[2][4], bh[2][4], bl[2][4];
#pragma unroll
            for (int mt = 0; mt < 2; mt++) {
                LDSM4(ah[mt], buf + aOff + mt * (16 * ROWB) + ko);
                LDSM4(al[mt], buf + MATB + aOff + mt * (16 * ROWB) + ko);
            }
#pragma unroll
            for (int t = 0; t < 2; t++) {
                LDSM4(bh[t], buf + 2*MATB + bOff + t * (16 * ROWB) + ko);
                LDSM4(bl[t], buf + 3*MATB + bOff + t * (16 * ROWB) + ko);
            }
#pragma unroll
            for (int mt = 0; mt < 2; mt++)
#pragma unroll
                for (int nt = 0; nt < 4; nt++) {
                    const uint32_t* Bh = &bh[nt >> 1][(nt & 1) * 2];
                    const uint32_t* Bl = &bl[nt >> 1][(nt & 1) * 2];
                    MMA_BF16(c[mt][nt], ah[mt], Bh[0], Bh[1]);
                    MMA_BF16(c[mt][nt], ah[mt], Bl[0], Bl[1]);
                    MMA_BF16(c[mt][nt], al[mt], Bh[0], Bh[1]);
                }
        }

        if (s + 1 < NSTAGE) {
            const uint32_t nb = sb + (uint32_t)((s + 1) & 1) * STAGEB;
            uint32_t h0, h1, l0, l1;
            cvt_f4(av0, h0, h1, l0, l1);
            STS64(nb + st0, h0, h1);           STS64(nb + MATB + st0, l0, l1);
            cvt_f4(av1, h0, h1, l0, l1);
            STS64(nb + st1, h0, h1);           STS64(nb + MATB + st1, l0, l1);
            cvt_f4(bv0, h0, h1, l0, l1);
            STS64(nb + 2*MATB + st0, h0, h1);  STS64(nb + 3*MATB + st0, l0, l1);
            cvt_f4(bv1, h0, h1, l0, l1);
            STS64(nb + 2*MATB + st1, h0, h1);  STS64(nb + 3*MATB + st1, l0, l1);
            __syncthreads();
        }
    }

    // Epilogue: C fragment rows {g, g+8}, cols pairs (2q, 2q+1) -> RoPE pairs
    const int g  = lane >> 2;
    const int qd = lane & 3;
    const bool doRope = ROPE && (nBase < (H_ + HKV_) * DH_);
#pragma unroll
    for (int mt = 0; mt < 2; mt++)
#pragma unroll
        for (int nt = 0; nt < 4; nt++) {
            const int colL = wn * 32 + nt * 8 + qd * 2;     // head-local column
            const int r0 = mBase + wm * 32 + mt * 16 + g;
            const int r1 = r0 + 8;
            float x0 = c[mt][nt][0], x1 = c[mt][nt][1];
            float y0 = c[mt][nt][2], y1 = c[mt][nt][3];
            if (doRope) {
                const int s0 = r0 & (S_ - 1);
                const int s1 = r1 & (S_ - 1);
                float c0 = __ldg(&cosp[s0 * DH_ + colL]);
                float n0 = __ldg(&sinp[s0 * DH_ + colL]);
                float c1 = __ldg(&cosp[s1 * DH_ + colL]);
                float n1 = __ldg(&sinp[s1 * DH_ + colL]);
                float t0 = x0 * c0 - x1 * n0;
                float t1 = x1 * c0 + x0 * n0;
                float u0 = y0 * c1 - y1 * n1;
                float u1 = y1 * c1 + y0 * n1;
                x0 = t0; x1 = t1; y0 = u0; y1 = u1;
            }
            float2 p0 = { x0, x1 };
            float2 p1 = { y0, y1 };
            *(float2*)&C[(size_t)r0 * Ncols + nBase + colL] = p0;
            *(float2*)&C[(size_t)r1 * Ncols + nBase + colL] = p1;
        }
}

// ---------------------------------------------------------------------------
// Flash-style attention, BQ=128, BK=64 (unchanged from the passing R6 run).
// ---------------------------------------------------------------------------
#define QS  132
#define KTS 68
#define VS  132
#define SS  68
#define ATTN_SMEM_BYTES (34688 * 4)

__global__ __launch_bounds__(256, 1)
void attn_kernel()
{
    extern __shared__ float sm[];
    float* sQ  = sm;
    float* sKV = sm + 16896;
    float* sS  = sm + 25600;
    float* sM  = sm + 34304;
    float* sL  = sm + 34432;
    float* sAl = sm + 34560;

    const int tid = threadIdx.x;
    const int tx = tid & 15;
    const int ty = tid >> 4;
    const int qt = blockIdx.x;
    const int h  = blockIdx.y;
    const int b  = blockIdx.z;

    const float SCALE = 0.08838834764831845f;

    const float* Qg = g_qkv + ((size_t)(b * S_) + qt * 128) * QKV_O + h * DH_;
    const float* Kg = g_qkv + (size_t)(b * S_) * QKV_O + (H_ + h) * DH_;
    const float* Vg = g_qkv + (size_t)(b * S_) * QKV_O + (H_ + HKV_ + h) * DH_;

    for (int idx = tid; idx < 128 * 32; idx += 256) {
        int r = idx >> 5, c4 = (idx & 31) << 2;
        *(float4*)&sQ[r * QS + c4] = *(const float4*)&Qg[(size_t)r * QKV_O + c4];
    }
    if (tid < 128) { sM[tid] = -1.0e30f; sL[tid] = 0.f; }

    float acc[8][8];
#pragma unroll
    for (int i = 0; i < 8; i++)
#pragma unroll
        for (int c = 0; c < 8; c++) acc[i][c] = 0.f;

    const int r0  = ty * 8;
    const int c0  = tx * 4;
    const int cv0 = tx * 8;

    float4 kpre[8];
#pragma unroll
    for (int u = 0; u < 8; u++) {
        int idx = tid + u * 256;
        int r = idx >> 5, c4 = (idx & 31) << 2;
        kpre[u] = *(const float4*)&Kg[(size_t)r * QKV_O + c4];
    }

    for (int kt = 0; kt < 32; kt++) {
        const float* Vt = Vg + (size_t)(kt * 64) * QKV_O;

        __syncthreads();
#pragma unroll
        for (int u = 0; u < 8; u++) {
            int idx = tid + u * 256;
            int r = idx >> 5, c4 = (idx & 31) << 2;
            sKV[(c4 + 0) * KTS + r] = kpre[u].x;
            sKV[(c4 + 1) * KTS + r] = kpre[u].y;
            sKV[(c4 + 2) * KTS + r] = kpre[u].z;
            sKV[(c4 + 3) * KTS + r] = kpre[u].w;
        }
        __syncthreads();

        float sacc[8][4];
#pragma unroll
        for (int i = 0; i < 8; i++)
#pragma unroll
            for (int j = 0; j < 4; j++) sacc[i][j] = 0.f;

        for (int d = 0; d < 128; d += 4) {
            float ka[4][4];
#pragma unroll
            for (int dd = 0; dd < 4; dd++) {
                float4 t = *(const float4*)&sKV[(d + dd) * KTS + c0];
                ka[dd][0]=t.x; ka[dd][1]=t.y; ka[dd][2]=t.z; ka[dd][3]=t.w;
            }
#pragma unroll
            for (int i = 0; i < 8; i++) {
                float4 q4 = *(const float4*)&sQ[(r0 + i) * QS + d];
                float qa[4] = { q4.x, q4.y, q4.z, q4.w };
#pragma unroll
                for (int dd = 0; dd < 4; dd++)
#pragma unroll
                    for (int j = 0; j < 4; j++)
                        sacc[i][j] = fmaf(qa[dd], ka[dd][j], sacc[i][j]);
            }
        }
#pragma unroll
        for (int i = 0; i < 8; i++) {
            float4 srow = { sacc[i][0]*SCALE, sacc[i][1]*SCALE,
                            sacc[i][2]*SCALE, sacc[i][3]*SCALE };
            *(float4*)&sS[(r0 + i) * SS + c0] = srow;
        }
        __syncthreads();

        for (int idx = tid; idx < 64 * 32; idx += 256) {
            int r = idx >> 5, c4 = (idx & 31) << 2;
            *(float4*)&sKV[r * VS + c4] = *(const float4*)&Vt[(size_t)r * QKV_O + c4];
        }

        {
            int row = tid >> 1;
            int g   = tid & 1;
            float* rowp = &sS[row * SS + g * 32];
            float4 v[8];
            float mx = -1.0e30f;
#pragma unroll
            for (int q = 0; q < 8; q++) {
                v[q] = *(float4*)&rowp[q * 4];
                mx = fmaxf(mx, fmaxf(fmaxf(v[q].x, v[q].y), fmaxf(v[q].z, v[q].w)));
            }
            mx = fmaxf(mx, __shfl_xor_sync(0xFFFFFFFFu, mx, 1));
            float mold = sM[row];
            float mnew = fmaxf(mold, mx);
            float sum = 0.f;
#pragma unroll
            for (int q = 0; q < 8; q++) {
                v[q].x = __expf(v[q].x - mnew);
                v[q].y = __expf(v[q].y - mnew);
                v[q].z = __expf(v[q].z - mnew);
                v[q].w = __expf(v[q].w - mnew);
                sum += (v[q].x + v[q].y) + (v[q].z + v[q].w);
                *(float4*)&rowp[q * 4] = v[q];
            }
            sum += __shfl_xor_sync(0xFFFFFFFFu, sum, 1);
            if (g == 0) {
                float al = __expf(mold - mnew);
                sL[row] = sL[row] * al + sum;
                sM[row] = mnew;
                sAl[row] = al;
            }
        }
        __syncthreads();

#pragma unroll
        for (int i = 0; i < 8; i++) {
            float al = sAl[r0 + i];
#pragma unroll
            for (int c = 0; c < 8; c++) acc[i][c] *= al;
        }

        if (kt + 1 < 32) {
            const float* Kn = Kg + (size_t)((kt + 1) * 64) * QKV_O;
#pragma unroll
            for (int u = 0; u < 8; u++) {
                int idx = tid + u * 256;
                int r = idx >> 5, c4 = (idx & 31) << 2;
                kpre[u] = *(const float4*)&Kn[(size_t)r * QKV_O + c4];
            }
        }

        for (int j = 0; j < 64; j++) {
            float4 v0 = *(const float4*)&sKV[j * VS + cv0];
            float4 v1 = *(const float4*)&sKV[j * VS + cv0 + 4];
#pragma unroll
            for (int i = 0; i < 8; i++) {
                float p = sS[(r0 + i) * SS + j];
                acc[i][0] = fmaf(p, v0.x, acc[i][0]);
                acc[i][1] = fmaf(p, v0.y, acc[i][1]);
                acc[i][2] = fmaf(p, v0.z, acc[i][2]);
                acc[i][3] = fmaf(p, v0.w, acc[i][3]);
                acc[i][4] = fmaf(p, v1.x, acc[i][4]);
                acc[i][5] = fmaf(p, v1.y, acc[i][5]);
                acc[i][6] = fmaf(p, v1.z, acc[i][6]);
                acc[i][7] = fmaf(p, v1.w, acc[i][7]);
            }
        }
    }

    float* Og = g_attn + ((size_t)(b * S_) + qt * 128) * (H_ * DH_) + h * DH_;
#pragma unroll
    for (int i = 0; i < 8; i++) {
        float linv = 1.f / sL[r0 + i];
        float4 o0 = { acc[i][0]*linv, acc[i][1]*linv, acc[i][2]*linv, acc[i][3]*linv };
        float4 o1 = { acc[i][4]*linv, acc[i][5]*linv, acc[i][6]*linv, acc[i][7]*linv };
        size_t off = (size_t)(r0 + i) * (H_ * DH_) + cv0;
        *(float4*)&Og[off]     = o0;
        *(float4*)&Og[off + 4] = o1;
    }
}

// ---------------------------------------------------------------------------
// Launch
// ---------------------------------------------------------------------------
extern "C" void kernel_launch(void* const* d_in, const int* in_sizes, int n_in,
                              void* d_out, int out_size)
{
    const float* hs   = (const float*)d_in[0];  // [2,2048,2048]
    const float* cosp = (const float*)d_in[1];  // [2048,128]
    const float* sinp = (const float*)d_in[2];  // [2048,128]
    const float* wqkv = (const float*)d_in[3];  // [6144,2048]
    const float* wo   = (const float*)d_in[4];  // [2048,2048]
    float* out = (float*)d_out;                 // [2,2048,2048]

    cudaFuncSetAttribute(mma_gemm<false, true, true>,
                         cudaFuncAttributeMaxDynamicSharedMemorySize, GEMM_SMEM);
    cudaFuncSetAttribute(mma_gemm<true, false, false>,
                         cudaFuncAttributeMaxDynamicSharedMemorySize, GEMM_SMEM);
    cudaFuncSetAttribute(attn_kernel,
                         cudaFuncAttributeMaxDynamicSharedMemorySize, ATTN_SMEM_BYTES);

    // 1. QKV projection + fused RoPE (mma.sync bf16 hi/lo)
    mma_gemm<false, true, true><<<dim3(QKV_O / 128, MROWS / 128), 512, GEMM_SMEM>>>(
        hs, wqkv, nullptr, cosp, sinp, QKV_O);

    // 2. Attention -> g_attn
    attn_kernel<<<dim3(S_ / 128, H_, B_), 256, ATTN_SMEM_BYTES>>>();

    // 3. Output projection (mma.sync bf16 hi/lo)
    mma_gemm<true, false, false><<<dim3(HID_ / 128, MROWS / 128), 512, GEMM_SMEM>>>(
        nullptr, wo, out, nullptr, nullptr, HID_);
}

// round 13
// speedup vs baseline: 2.4648x; 1.6491x over previous
#include <cuda_runtime.h>
#include <cuda_bf16.h>
#include <math.h>
#include <stdint.h>

// Problem constants
#define B_   2
#define S_   2048
#define HID_ 2048
#define H_   16
#define HKV_ 16
#define DH_  128
#define QKV_O 6144
#define MROWS 4096

// Scratch (allocation-free rule: __device__ globals)
__device__ float g_qkv[(size_t)B_ * S_ * QKV_O];     // [B,S,6144]
__device__ float g_attn[(size_t)B_ * S_ * H_ * DH_]; // [B,S,2048]

// ---------------------------------------------------------------------------
// Portable tensor-core primitives (sm_80+ PTX; legal on compute_103)
// ---------------------------------------------------------------------------
__device__ __forceinline__ uint32_t smem_u32(const void* p) {
    uint32_t a;
    asm("{ .reg .u64 t; cvta.to.shared.u64 t, %1; cvt.u32.u64 %0, t; }"
        : "=r"(a) : "l"(p));
    return a;
}
#define LDSM4(r, addr) \
    asm volatile("ldmatrix.sync.aligned.m8n8.x4.shared.b16 {%0,%1,%2,%3}, [%4];" \
        : "=r"((r)[0]), "=r"((r)[1]), "=r"((r)[2]), "=r"((r)[3]) : "r"(addr))
#define LDSM4T(r, addr) \
    asm volatile("ldmatrix.sync.aligned.m8n8.x4.trans.shared.b16 {%0,%1,%2,%3}, [%4];" \
        : "=r"((r)[0]), "=r"((r)[1]), "=r"((r)[2]), "=r"((r)[3]) : "r"(addr))
#define MMA_BF16(c, a, b0, b1) \
    asm volatile("mma.sync.aligned.m16n8k16.row.col.f32.bf16.bf16.f32 " \
        "{%0,%1,%2,%3}, {%4,%5,%6,%7}, {%8,%9}, {%0,%1,%2,%3};" \
        : "+f"((c)[0]), "+f"((c)[1]), "+f"((c)[2]), "+f"((c)[3]) \
        : "r"((a)[0]), "r"((a)[1]), "r"((a)[2]), "r"((a)[3]), "r"(b0), "r"(b1))
#define STS64(addr, u0, u1) \
    asm volatile("st.shared.v2.b32 [%0], {%1, %2};" \
        :: "r"(addr), "r"(u0), "r"(u1) : "memory")

// Split float4 -> bf16 hi pair-packed (h0,h1) + residual lo (l0,l1)
__device__ __forceinline__ void cvt_f4(const float4 f,
                                       uint32_t& h0, uint32_t& h1,
                                       uint32_t& l0, uint32_t& l1)
{
    __nv_bfloat16 bx = __float2bfloat16(f.x);
    __nv_bfloat16 by = __float2bfloat16(f.y);
    __nv_bfloat16 bz = __float2bfloat16(f.z);
    __nv_bfloat16 bw = __float2bfloat16(f.w);
    float rx = f.x - __bfloat162float(bx);
    float ry = f.y - __bfloat162float(by);
    float rz = f.z - __bfloat162float(bz);
    float rw = f.w - __bfloat162float(bw);
    __nv_bfloat162 hxy = __halves2bfloat162(bx, by);
    __nv_bfloat162 hzw = __halves2bfloat162(bz, bw);
    __nv_bfloat162 lxy = __floats2bfloat162_rn(rx, ry);
    __nv_bfloat162 lzw = __floats2bfloat162_rn(rz, rw);
    h0 = *reinterpret_cast<uint32_t*>(&hxy);
    h1 = *reinterpret_cast<uint32_t*>(&hzw);
    l0 = *reinterpret_cast<uint32_t*>(&lxy);
    l1 = *reinterpret_cast<uint32_t*>(&lzw);
}

// ---------------------------------------------------------------------------
// Tensor-core NT GEMM (validated R12: 995us QKV, tensor=51%). Unchanged.
// ---------------------------------------------------------------------------
#define GK        2048
#define NSTAGE    64
#define ROWB      80
#define MATB      (128 * ROWB)
#define STAGEB    (4 * MATB)
#define GEMM_SMEM (2 * STAGEB)

template<bool A_FROM_ATTN, bool C_TO_QKV, bool ROPE>
__global__ __launch_bounds__(512, 1)
void mma_gemm(const float* __restrict__ Ap, const float* __restrict__ Bp,
              float* __restrict__ Cp,
              const float* __restrict__ cosp, const float* __restrict__ sinp,
              int Ncols)
{
    extern __shared__ char smem[];
    const uint32_t sb = smem_u32(smem);
    const int tid  = threadIdx.x;
    const int lane = tid & 31;
    const int warp = tid >> 5;
    const int wm = warp >> 2;
    const int wn = warp & 3;
    const int mBase = blockIdx.y * 128;
    const int nBase = blockIdx.x * 128;

    const float* A = A_FROM_ATTN ? (const float*)g_attn : Ap;
    float*       C = C_TO_QKV   ? (float*)g_qkv        : Cp;

    const int i0 = tid, i1 = tid + 512;
    const float* gA0 = A  + (size_t)(mBase + (i0 >> 3)) * GK + (i0 & 7) * 4;
    const float* gA1 = A  + (size_t)(mBase + (i1 >> 3)) * GK + (i1 & 7) * 4;
    const float* gB0 = Bp + (size_t)(nBase + (i0 >> 3)) * GK + (i0 & 7) * 4;
    const float* gB1 = Bp + (size_t)(nBase + (i1 >> 3)) * GK + (i1 & 7) * 4;
    const uint32_t st0 = (uint32_t)((i0 >> 3) * ROWB + (i0 & 7) * 8);
    const uint32_t st1 = (uint32_t)((i1 >> 3) * ROWB + (i1 & 7) * 8);

    const uint32_t aOff = (uint32_t)((wm * 32 + (lane & 15)) * ROWB + (lane >> 4) * 16);
    const uint32_t bOff = (uint32_t)((wn * 32 + ((lane >> 3) & 2) * 4 + (lane & 7)) * ROWB
                                     + ((lane >> 3) & 1) * 16);

    float c[2][4][4];
#pragma unroll
    for (int mt = 0; mt < 2; mt++)
#pragma unroll
        for (int nt = 0; nt < 4; nt++)
#pragma unroll
            for (int q = 0; q < 4; q++) c[mt][nt][q] = 0.f;

    {
        float4 av0 = *(const float4*)gA0;
        float4 av1 = *(const float4*)gA1;
        float4 bv0 = *(const float4*)gB0;
        float4 bv1 = *(const float4*)gB1;
        uint32_t h0, h1, l0, l1;
        cvt_f4(av0, h0, h1, l0, l1);
        STS64(sb + st0, h0, h1);           STS64(sb + MATB + st0, l0, l1);
        cvt_f4(av1, h0, h1, l0, l1);
        STS64(sb + st1, h0, h1);           STS64(sb + MATB + st1, l0, l1);
        cvt_f4(bv0, h0, h1, l0, l1);
        STS64(sb + 2*MATB + st0, h0, h1);  STS64(sb + 3*MATB + st0, l0, l1);
        cvt_f4(bv1, h0, h1, l0, l1);
        STS64(sb + 2*MATB + st1, h0, h1);  STS64(sb + 3*MATB + st1, l0, l1);
    }
    __syncthreads();

    for (int s = 0; s < NSTAGE; s++) {
        float4 av0, av1, bv0, bv1;
        if (s + 1 < NSTAGE) {
            const size_t ko = (size_t)(s + 1) * 32;
            av0 = *(const float4*)(gA0 + ko);
            av1 = *(const float4*)(gA1 + ko);
            bv0 = *(const float4*)(gB0 + ko);
            bv1 = *(const float4*)(gB1 + ko);
        }

        const uint32_t buf = sb + (uint32_t)(s & 1) * STAGEB;
#pragma unroll
        for (int kb = 0; kb < 2; kb++) {
            const uint32_t ko = kb * 32;
            uint32_t ah[2][4], al[2][4], bh[2][4], bl[2][4];
#pragma unroll
            for (int mt = 0; mt < 2; mt++) {
                LDSM4(ah[mt], buf + aOff + mt * (16 * ROWB) + ko);
                LDSM4(al[mt], buf + MATB + aOff + mt * (16 * ROWB) + ko);
            }
#pragma unroll
            for (int t = 0; t < 2; t++) {
                LDSM4(bh[t], buf + 2*MATB + bOff + t * (16 * ROWB) + ko);
                LDSM4(bl[t], buf + 3*MATB + bOff + t * (16 * ROWB) + ko);
            }
#pragma unroll
            for (int mt = 0; mt < 2; mt++)
#pragma unroll
                for (int nt = 0; nt < 4; nt++) {
                    const uint32_t* Bh = &bh[nt >> 1][(nt & 1) * 2];
                    const uint32_t* Bl = &bl[nt >> 1][(nt & 1) * 2];
                    MMA_BF16(c[mt][nt], ah[mt], Bh[0], Bh[1]);
                    MMA_BF16(c[mt][nt], ah[mt], Bl[0], Bl[1]);
                    MMA_BF16(c[mt][nt], al[mt], Bh[0], Bh[1]);
                }
        }

        if (s + 1 < NSTAGE) {
            const uint32_t nb = sb + (uint32_t)((s + 1) & 1) * STAGEB;
            uint32_t h0, h1, l0, l1;
            cvt_f4(av0, h0, h1, l0, l1);
            STS64(nb + st0, h0, h1);           STS64(nb + MATB + st0, l0, l1);
            cvt_f4(av1, h0, h1, l0, l1);
            STS64(nb + st1, h0, h1);           STS64(nb + MATB + st1, l0, l1);
            cvt_f4(bv0, h0, h1, l0, l1);
            STS64(nb + 2*MATB + st0, h0, h1);  STS64(nb + 3*MATB + st0, l0, l1);
            cvt_f4(bv1, h0, h1, l0, l1);
            STS64(nb + 2*MATB + st1, h0, h1);  STS64(nb + 3*MATB + st1, l0, l1);
            __syncthreads();
        }
    }

    const int g  = lane >> 2;
    const int qd = lane & 3;
    const bool doRope = ROPE && (nBase < (H_ + HKV_) * DH_);
#pragma unroll
    for (int mt = 0; mt < 2; mt++)
#pragma unroll
        for (int nt = 0; nt < 4; nt++) {
            const int colL = wn * 32 + nt * 8 + qd * 2;
            const int r0 = mBase + wm * 32 + mt * 16 + g;
            const int r1 = r0 + 8;
            float x0 = c[mt][nt][0], x1 = c[mt][nt][1];
            float y0 = c[mt][nt][2], y1 = c[mt][nt][3];
            if (doRope) {
                const int s0 = r0 & (S_ - 1);
                const int s1 = r1 & (S_ - 1);
                float c0 = __ldg(&cosp[s0 * DH_ + colL]);
                float n0 = __ldg(&sinp[s0 * DH_ + colL]);
                float c1 = __ldg(&cosp[s1 * DH_ + colL]);
                float n1 = __ldg(&sinp[s1 * DH_ + colL]);
                float t0 = x0 * c0 - x1 * n0;
                float t1 = x1 * c0 + x0 * n0;
                float u0 = y0 * c1 - y1 * n1;
                float u1 = y1 * c1 + y0 * n1;
                x0 = t0; x1 = t1; y0 = u0; y1 = u1;
            }
            float2 p0 = { x0, x1 };
            float2 p1 = { y0, y1 };
            *(float2*)&C[(size_t)r0 * Ncols + nBase + colL] = p0;
            *(float2*)&C[(size_t)r1 * Ncols + nBase + colL] = p1;
        }
}

// ---------------------------------------------------------------------------
// Tensor-core flash attention. BQ=64, BK=64, DH=128. 256 threads (8 warps,
// 2m x 4n). bf16 hi/lo (3-pass) for both QK^T and PV.
// Chunked smem layout (32 bf16 per row, ROWB=80) identical to validated GEMM.
// V loaded non-transposed (staged like K); PV B-operand via ldmatrix.trans.
// Smem (bytes):
//   QH 0        QL 20480   KH 40960   KL 61440
//   VH 81920    VL 102400  PH 122880  PL 133120
//   SS 143360 (fp32 [64][68] = 17408)
//   SM 160768   SL 161024  SAL 161280   total 161536
// ---------------------------------------------------------------------------
#define AQH 0
#define AQL 20480
#define AKH 40960
#define AKL 61440
#define AVH 81920
#define AVL 102400
#define APH 122880
#define APL 133120
#define ASS 143360
#define ASM 160768
#define ASL 161024
#define AAL 161280
#define ATTN_SMEM 161536
#define CHB 5120                    // chunk bytes: 64 rows * 80

__global__ __launch_bounds__(256, 1)
void attn_mma()
{
    extern __shared__ char smem[];
    const uint32_t sb = smem_u32(smem);
    float* sS  = (float*)(smem + ASS);
    float* sM  = (float*)(smem + ASM);
    float* sL  = (float*)(smem + ASL);
    float* sAl = (float*)(smem + AAL);

    const int tid  = threadIdx.x;
    const int lane = tid & 31;
    const int warp = tid >> 5;
    const int wms = warp & 1;          // m warp (2)
    const int wns = warp >> 1;         // n warp (4)
    const int qt = blockIdx.x;         // 32 q-tiles of 64
    const int h  = blockIdx.y;
    const int b  = blockIdx.z;

    const float SCALE = 0.08838834764831845f;

    const float* Qg = g_qkv + ((size_t)(b * S_) + qt * 64) * QKV_O + h * DH_;
    const float* Kg = g_qkv + (size_t)(b * S_) * QKV_O + (H_ + h) * DH_;
    const float* Vg = g_qkv + (size_t)(b * S_) * QKV_O + (H_ + HKV_ + h) * DH_;

    // Stage Q (hi/lo, chunked): 2048 float4s, 8 per thread
#pragma unroll
    for (int u = 0; u < 8; u++) {
        int idx = tid + u * 256;
        int row = idx >> 5, c4 = idx & 31;
        float4 v = *(const float4*)&Qg[(size_t)row * QKV_O + c4 * 4];
        uint32_t h0, h1, l0, l1;
        cvt_f4(v, h0, h1, l0, l1);
        uint32_t off = (uint32_t)((c4 >> 3) * CHB + row * ROWB + (c4 & 7) * 8);
        STS64(sb + AQH + off, h0, h1);
        STS64(sb + AQL + off, l0, l1);
    }
    if (tid < 64) { sM[tid] = -1.0e30f; sL[tid] = 0.f; }

    float co[2][4][4];
#pragma unroll
    for (int mt = 0; mt < 2; mt++)
#pragma unroll
        for (int nt = 0; nt < 4; nt++)
#pragma unroll
            for (int q = 0; q < 4; q++) co[mt][nt][q] = 0.f;

    // ldmatrix base offsets
    const uint32_t aRow = (uint32_t)((wms * 32 + (lane & 15)) * ROWB + (lane >> 4) * 16);
    const uint32_t bRowS = (uint32_t)((wns * 16 + ((lane >> 3) & 2) * 4 + (lane & 7)) * ROWB
                                      + ((lane >> 3) & 1) * 16);
    const int g  = lane >> 2;
    const int qd = lane & 3;

    for (int kt = 0; kt < 32; kt++) {
        __syncthreads();   // protect prior PV reads of V / P buffers

        // Stage K, V tiles (hi/lo, chunked)
        const float* Kt = Kg + (size_t)(kt * 64) * QKV_O;
        const float* Vt = Vg + (size_t)(kt * 64) * QKV_O;
#pragma unroll
        for (int u = 0; u < 8; u++) {
            int idx = tid + u * 256;
            int row = idx >> 5, c4 = idx & 31;
            uint32_t off = (uint32_t)((c4 >> 3) * CHB + row * ROWB + (c4 & 7) * 8);
            float4 kv = *(const float4*)&Kt[(size_t)row * QKV_O + c4 * 4];
            uint32_t h0, h1, l0, l1;
            cvt_f4(kv, h0, h1, l0, l1);
            STS64(sb + AKH + off, h0, h1);
            STS64(sb + AKL + off, l0, l1);
            float4 vv = *(const float4*)&Vt[(size_t)row * QKV_O + c4 * 4];
            cvt_f4(vv, h0, h1, l0, l1);
            STS64(sb + AVH + off, h0, h1);
            STS64(sb + AVL + off, l0, l1);
        }
        __syncthreads();

        // ---- S = Q K^T (64x64, K-dim 128 = 4 chunks x 2 sub) ----
        float cs[2][2][4];
#pragma unroll
        for (int mt = 0; mt < 2; mt++)
#pragma unroll
            for (int nt = 0; nt < 2; nt++)
#pragma unroll
                for (int q = 0; q < 4; q++) cs[mt][nt][q] = 0.f;

#pragma unroll
        for (int c = 0; c < 4; c++)
#pragma unroll
            for (int sub = 0; sub < 2; sub++) {
                const uint32_t ko = (uint32_t)(c * CHB + sub * 32);
                uint32_t aqh[2][4], aql[2][4], bkh[4], bkl[4];
#pragma unroll
                for (int mt = 0; mt < 2; mt++) {
                    LDSM4(aqh[mt], sb + AQH + ko + aRow + mt * (16 * ROWB));
                    LDSM4(aql[mt], sb + AQL + ko + aRow + mt * (16 * ROWB));
                }
                LDSM4(bkh, sb + AKH + ko + bRowS);
                LDSM4(bkl, sb + AKL + ko + bRowS);
#pragma unroll
                for (int mt = 0; mt < 2; mt++)
#pragma unroll
                    for (int nt = 0; nt < 2; nt++) {
                        MMA_BF16(cs[mt][nt], aqh[mt], bkh[nt*2], bkh[nt*2+1]);
                        MMA_BF16(cs[mt][nt], aql[mt], bkh[nt*2], bkh[nt*2+1]);
                        MMA_BF16(cs[mt][nt], aqh[mt], bkl[nt*2], bkl[nt*2+1]);
                    }
            }

        // Write S*SCALE to sS (fp32)
#pragma unroll
        for (int mt = 0; mt < 2; mt++)
#pragma unroll
            for (int nt = 0; nt < 2; nt++) {
                const int col = wns * 16 + nt * 8 + qd * 2;
                const int r0 = wms * 32 + mt * 16 + g;
                float2 p0 = { cs[mt][nt][0] * SCALE, cs[mt][nt][1] * SCALE };
                float2 p1 = { cs[mt][nt][2] * SCALE, cs[mt][nt][3] * SCALE };
                *(float2*)&sS[r0 * 68 + col]       = p0;
                *(float2*)&sS[(r0 + 8) * 68 + col] = p1;
            }
        __syncthreads();

        // ---- Online softmax (4 threads/row) + P -> bf16 hi/lo convert ----
        {
            const int row = tid >> 2;
            const int gch = tid & 3;
            float* rowp = &sS[row * 68 + gch * 16];
            float4 v[4];
            float mx = -1.0e30f;
#pragma unroll
            for (int q = 0; q < 4; q++) {
                v[q] = *(float4*)&rowp[q * 4];
                mx = fmaxf(mx, fmaxf(fmaxf(v[q].x, v[q].y), fmaxf(v[q].z, v[q].w)));
            }
            mx = fmaxf(mx, __shfl_xor_sync(0xFFFFFFFFu, mx, 1));
            mx = fmaxf(mx, __shfl_xor_sync(0xFFFFFFFFu, mx, 2));
            float mold = sM[row];
            float mnew = fmaxf(mold, mx);
            float sum = 0.f;
#pragma unroll
            for (int q = 0; q < 4; q++) {
                v[q].x = __expf(v[q].x - mnew);
                v[q].y = __expf(v[q].y - mnew);
                v[q].z = __expf(v[q].z - mnew);
                v[q].w = __expf(v[q].w - mnew);
                sum += (v[q].x + v[q].y) + (v[q].z + v[q].w);
            }
            sum += __shfl_xor_sync(0xFFFFFFFFu, sum, 1);
            sum += __shfl_xor_sync(0xFFFFFFFFu, sum, 2);
            if (gch == 0) {
                float al = __expf(mold - mnew);
                sL[row] = sL[row] * al + sum;
                sM[row] = mnew;
                sAl[row] = al;
            }
            // Convert p (in regs) to Ph/Pl chunks
#pragma unroll
            for (int q = 0; q < 4; q++) {
                const int cb = gch * 16 + q * 4;
                uint32_t off = (uint32_t)((cb >> 5) * CHB + row * ROWB + (cb & 31) * 2);
                uint32_t h0, h1, l0, l1;
                cvt_f4(v[q], h0, h1, l0, l1);
                STS64(sb + APH + off, h0, h1);
                STS64(sb + APL + off, l0, l1);
            }
        }
        __syncthreads();

        // ---- Rescale O accumulators ----
#pragma unroll
        for (int mt = 0; mt < 2; mt++) {
            const int r0 = wms * 32 + mt * 16 + g;
            const float al0 = sAl[r0];
            const float al1 = sAl[r0 + 8];
#pragma unroll
            for (int nt = 0; nt < 4; nt++) {
                co[mt][nt][0] *= al0; co[mt][nt][1] *= al0;
                co[mt][nt][2] *= al1; co[mt][nt][3] *= al1;
            }
        }

        // ---- O += P V  (64x128, K-dim 64 = 2 chunks x 2 sub) ----
#pragma unroll
        for (int ch = 0; ch < 2; ch++)
#pragma unroll
            for (int sub = 0; sub < 2; sub++) {
                const uint32_t pko = (uint32_t)(ch * CHB + sub * 32);
                const int krow = ch * 32 + sub * 16;
                uint32_t aph[2][4], apl[2][4], bvh[2][4], bvl[2][4];
#pragma unroll
                for (int mt = 0; mt < 2; mt++) {
                    LDSM4(aph[mt], sb + APH + pko + aRow + mt * (16 * ROWB));
                    LDSM4(apl[mt], sb + APL + pko + aRow + mt * (16 * ROWB));
                }
#pragma unroll
                for (int t = 0; t < 2; t++) {
                    const uint32_t va = (uint32_t)(wns * CHB
                        + (krow + (lane & 15)) * ROWB + (lane >> 4) * 16 + t * 32);
                    LDSM4T(bvh[t], sb + AVH + va);
                    LDSM4T(bvl[t], sb + AVL + va);
                }
#pragma unroll
                for (int mt = 0; mt < 2; mt++)
#pragma unroll
                    for (int nt = 0; nt < 4; nt++) {
                        const uint32_t* Bh = &bvh[nt >> 1][(nt & 1) * 2];
                        const uint32_t* Bl = &bvl[nt >> 1][(nt & 1) * 2];
                        MMA_BF16(co[mt][nt], aph[mt], Bh[0], Bh[1]);
                        MMA_BF16(co[mt][nt], apl[mt], Bh[0], Bh[1]);
                        MMA_BF16(co[mt][nt], aph[mt], Bl[0], Bl[1]);
                    }
            }
    }

    // ---- Write O (divide by final l) ----
    float* Og = g_attn + ((size_t)(b * S_) + qt * 64) * (H_ * DH_) + h * DH_;
#pragma unroll
    for (int mt = 0; mt < 2; mt++) {
        const int r0 = wms * 32 + mt * 16 + g;
        const float li0 = 1.f / sL[r0];
        const float li1 = 1.f / sL[r0 + 8];
#pragma unroll
        for (int nt = 0; nt < 4; nt++) {
            const int col = wns * 32 + nt * 8 + qd * 2;
            float2 p0 = { co[mt][nt][0] * li0, co[mt][nt][1] * li0 };
            float2 p1 = { co[mt][nt][2] * li1, co[mt][nt][3] * li1 };
            *(float2*)&Og[(size_t)r0 * (H_ * DH_) + col]       = p0;
            *(float2*)&Og[(size_t)(r0 + 8) * (H_ * DH_) + col] = p1;
        }
    }
}

// ---------------------------------------------------------------------------
// Launch
// ---------------------------------------------------------------------------
extern "C" void kernel_launch(void* const* d_in, const int* in_sizes, int n_in,
                              void* d_out, int out_size)
{
    const float* hs   = (const float*)d_in[0];
    const float* cosp = (const float*)d_in[1];
    const float* sinp = (const float*)d_in[2];
    const float* wqkv = (const float*)d_in[3];
    const float* wo   = (const float*)d_in[4];
    float* out = (float*)d_out;

    cudaFuncSetAttribute(mma_gemm<false, true, true>,
                         cudaFuncAttributeMaxDynamicSharedMemorySize, GEMM_SMEM);
    cudaFuncSetAttribute(mma_gemm<true, false, false>,
                         cudaFuncAttributeMaxDynamicSharedMemorySize, GEMM_SMEM);
    cudaFuncSetAttribute(attn_mma,
                         cudaFuncAttributeMaxDynamicSharedMemorySize, ATTN_SMEM);

    // 1. QKV projection + fused RoPE (mma.sync bf16 hi/lo)
    mma_gemm<false, true, true><<<dim3(QKV_O / 128, MROWS / 128), 512, GEMM_SMEM>>>(
        hs, wqkv, nullptr, cosp, sinp, QKV_O);

    // 2. Attention (tensor-core) -> g_attn
    attn_mma<<<dim3(S_ / 64, H_, B_), 256, ATTN_SMEM>>>();

    // 3. Output projection (mma.sync bf16 hi/lo)
    mma_gemm<true, false, false><<<dim3(HID_ / 128, MROWS / 128), 512, GEMM_SMEM>>>(
        nullptr, wo, out, nullptr, nullptr, HID_);
}